// round 14
// baseline (speedup 1.0000x reference)
#include <cuda_runtime.h>
#include <cuda_bf16.h>

typedef unsigned long long u64;
typedef unsigned int u32;

// ---------------- packed f32x2 helpers ----------------
__device__ __forceinline__ u64 pk2(float lo, float hi) {
    u64 r; asm("mov.b64 %0,{%1,%2};" : "=l"(r) : "f"(lo), "f"(hi)); return r;
}
__device__ __forceinline__ float2 upk2(u64 v) {
    float2 f; asm("mov.b64 {%0,%1},%2;" : "=f"(f.x), "=f"(f.y) : "l"(v)); return f;
}
__device__ __forceinline__ u64 fma2(u64 a, u64 b, u64 c) {
    u64 d; asm("fma.rn.f32x2 %0,%1,%2,%3;" : "=l"(d) : "l"(a), "l"(b), "l"(c)); return d;
}
__device__ __forceinline__ u64 add2(u64 a, u64 b) {
    u64 d; asm("add.rn.f32x2 %0,%1,%2;" : "=l"(d) : "l"(a), "l"(b)); return d;
}

// ---------------- HMMA m16n8k16 row.col f32.bf16.bf16.f32 ----------------
__device__ __forceinline__ void mma_bf16(float& d0, float& d1, float& d2, float& d3,
                                         u32 a0, u32 a1, u32 a2, u32 a3,
                                         u32 b0, u32 b1) {
    asm volatile(
        "mma.sync.aligned.m16n8k16.row.col.f32.bf16.bf16.f32 "
        "{%0,%1,%2,%3}, {%4,%5,%6,%7}, {%8,%9}, {%0,%1,%2,%3};"
        : "+f"(d0), "+f"(d1), "+f"(d2), "+f"(d3)
        : "r"(a0), "r"(a1), "r"(a2), "r"(a3), "r"(b0), "r"(b1));
}

// two floats -> bf16x2 hi + bf16x2 residual lo (bit-op reconstruction + packed fma)
__device__ __forceinline__ void split2(float v0, float v1, u32& h, u32& l) {
    __nv_bfloat162 hb = __float22bfloat162_rn(make_float2(v0, v1));
    h = *reinterpret_cast<u32*>(&hb);
    const float f0 = __uint_as_float(h << 16);
    const float f1 = __uint_as_float(h & 0xffff0000u);
    const u64 r = fma2(pk2(f0, f1), 0xBF800000BF800000ull /*(-1,-1)*/, pk2(v0, v1));
    const float2 rf = upk2(r);
    __nv_bfloat162 lb = __float22bfloat162_rn(make_float2(rf.x, rf.y));
    l = *reinterpret_cast<u32*>(&lb);
}

__device__ __forceinline__ u64 shflx(u64 v, int m) {
    return (u64)__shfl_xor_sync(0xffffffffu, (unsigned long long)v, m);
}

#define TPB    128
#define NCTAS  592   // 148 SM * 4

// raw x loads for one 16-row group (k-permuted: lane quad t reads cols [4t,4t+3])
__device__ __forceinline__ void load_x(const float* __restrict__ x, int R, int g, int t,
                                       int N, float4 q0[4], float4 q1[4]) {
    int r0 = R + g;     if (r0 > N - 1) r0 = N - 1;
    int r1 = R + g + 8; if (r1 > N - 1) r1 = N - 1;
    const float4* p0 = (const float4*)(x + (size_t)r0 * 64 + 4 * t);
    const float4* p1 = (const float4*)(x + (size_t)r1 * 64 + 4 * t);
    #pragma unroll
    for (int kb = 0; kb < 4; kb++) { q0[kb] = p0[kb * 4]; q1[kb] = p1[kb * 4]; }
}

// full epilogue for one 16-row group, operating on its layer-1 D fragments
__device__ __forceinline__ void epilogue(
    const float d1[4][4], int R, int N, int HW, int lane, int g, int t,
    float bb0, float bb1, float bb2,
    const ulonglong2* __restrict__ sG1, const ulonglong2* __restrict__ sB1,   // [2][32] flat
    const uint4* __restrict__ sW2H, const uint4* __restrict__ sW2L,           // [2][32] flat
    const uint4* __restrict__ sW3F,                                           // [32]
    const ulonglong2* __restrict__ sG2, const ulonglong2* __restrict__ sB2,   // [32]
    float* __restrict__ out)
{
    // ---- LN1 in frag layout: quad shuffle stats ----
    u64 ss = 0ull, qq = 0ull;
    #pragma unroll
    for (int nb = 0; nb < 4; nb++) {
        const u64 m0 = pk2(d1[nb][0], d1[nb][2]);
        const u64 m1 = pk2(d1[nb][1], d1[nb][3]);
        ss = add2(ss, add2(m0, m1));
        qq = fma2(m0, m0, fma2(m1, m1, qq));
    }
    ss = add2(ss, shflx(ss, 1)); ss = add2(ss, shflx(ss, 2));
    qq = add2(qq, shflx(qq, 1)); qq = add2(qq, shflx(qq, 2));
    float2 sv = upk2(ss), qv = upk2(qq);
    const float mgA = sv.x * (1.0f/32.0f), mgB = sv.y * (1.0f/32.0f);
    const float scA = rsqrtf(qv.x * (1.0f/32.0f) - mgA * mgA + 1e-5f);
    const float scB = rsqrtf(qv.y * (1.0f/32.0f) - mgB * mgB + 1e-5f);
    const u64 scpA = pk2(scA, scA), nmpA = pk2(-mgA*scA, -mgA*scA);
    const u64 scpB = pk2(scB, scB), nmpB = pk2(-mgB*scB, -mgB*scB);

    const ulonglong2 g1a = sG1[lane], g1b = sG1[32 + lane];
    const ulonglong2 b1a = sB1[lane], b1b = sB1[32 + lane];
    const u64 g1p[4] = {g1a.x, g1a.y, g1b.x, g1b.y};
    const u64 b1p[4] = {b1a.x, b1a.y, b1b.x, b1b.y};

    u32 hh[4][2], hl[4][2];
    #pragma unroll
    for (int nb = 0; nb < 4; nb++) {
        u64 u0 = fma2(fma2(pk2(d1[nb][0], d1[nb][1]), scpA, nmpA), g1p[nb], b1p[nb]);
        u64 u1 = fma2(fma2(pk2(d1[nb][2], d1[nb][3]), scpB, nmpB), g1p[nb], b1p[nb]);
        float2 f0 = upk2(u0), f1 = upk2(u1);
        split2(fmaxf(f0.x, 0.f), fmaxf(f0.y, 0.f), hh[nb][0], hl[nb][0]);
        split2(fmaxf(f1.x, 0.f), fmaxf(f1.y, 0.f), hh[nb][1], hl[nb][1]);
    }

    // ---- layer 2 on HMMA (w2 frags from smem) ----
    const uint4 w2h0 = sW2H[lane], w2h1 = sW2H[32 + lane];
    const uint4 w2l0 = sW2L[lane], w2l1 = sW2L[32 + lane];

    float d2f[2][4];
    {
        float d0 = 0.f, dd1 = 0.f, d2 = 0.f, d3 = 0.f;
        mma_bf16(d0,dd1,d2,d3, hh[0][0],hh[0][1],hh[1][0],hh[1][1], w2h0.x, w2h0.y);
        mma_bf16(d0,dd1,d2,d3, hh[0][0],hh[0][1],hh[1][0],hh[1][1], w2l0.x, w2l0.y);
        mma_bf16(d0,dd1,d2,d3, hl[0][0],hl[0][1],hl[1][0],hl[1][1], w2h0.x, w2h0.y);
        mma_bf16(d0,dd1,d2,d3, hh[2][0],hh[2][1],hh[3][0],hh[3][1], w2h1.x, w2h1.y);
        mma_bf16(d0,dd1,d2,d3, hh[2][0],hh[2][1],hh[3][0],hh[3][1], w2l1.x, w2l1.y);
        mma_bf16(d0,dd1,d2,d3, hl[2][0],hl[2][1],hl[3][0],hl[3][1], w2h1.x, w2h1.y);
        d2f[0][0] = d0; d2f[0][1] = dd1; d2f[0][2] = d2; d2f[0][3] = d3;
        d0 = 0.f; dd1 = 0.f; d2 = 0.f; d3 = 0.f;
        mma_bf16(d0,dd1,d2,d3, hh[0][0],hh[0][1],hh[1][0],hh[1][1], w2h0.z, w2h0.w);
        mma_bf16(d0,dd1,d2,d3, hh[0][0],hh[0][1],hh[1][0],hh[1][1], w2l0.z, w2l0.w);
        mma_bf16(d0,dd1,d2,d3, hl[0][0],hl[0][1],hl[1][0],hl[1][1], w2h0.z, w2h0.w);
        mma_bf16(d0,dd1,d2,d3, hh[2][0],hh[2][1],hh[3][0],hh[3][1], w2h1.z, w2h1.w);
        mma_bf16(d0,dd1,d2,d3, hh[2][0],hh[2][1],hh[3][0],hh[3][1], w2l1.z, w2l1.w);
        mma_bf16(d0,dd1,d2,d3, hl[2][0],hl[2][1],hl[3][0],hl[3][1], w2h1.z, w2h1.w);
        d2f[1][0] = d0; d2f[1][1] = dd1; d2f[1][2] = d2; d2f[1][3] = d3;
    }

    // ---- LN2 ----
    u64 ss2 = 0ull, qq2 = 0ull;
    #pragma unroll
    for (int nb2 = 0; nb2 < 2; nb2++) {
        const u64 m0 = pk2(d2f[nb2][0], d2f[nb2][2]);
        const u64 m1 = pk2(d2f[nb2][1], d2f[nb2][3]);
        ss2 = add2(ss2, add2(m0, m1));
        qq2 = fma2(m0, m0, fma2(m1, m1, qq2));
    }
    ss2 = add2(ss2, shflx(ss2, 1)); ss2 = add2(ss2, shflx(ss2, 2));
    qq2 = add2(qq2, shflx(qq2, 1)); qq2 = add2(qq2, shflx(qq2, 2));
    float2 sv2 = upk2(ss2), qv2 = upk2(qq2);
    const float m2A = sv2.x * (1.0f/16.0f), m2B = sv2.y * (1.0f/16.0f);
    const float s2A = rsqrtf(qv2.x * (1.0f/16.0f) - m2A * m2A + 1e-5f);
    const float s2B = rsqrtf(qv2.y * (1.0f/16.0f) - m2B * m2B + 1e-5f);
    const u64 sc2pA = pk2(s2A, s2A), nm2pA = pk2(-m2A*s2A, -m2A*s2A);
    const u64 sc2pB = pk2(s2B, s2B), nm2pB = pk2(-m2B*s2B, -m2B*s2B);

    const ulonglong2 g2q = sG2[lane], b2q = sB2[lane];
    const u64 g2p[2] = {g2q.x, g2q.y};
    const u64 b2p[2] = {b2q.x, b2q.y};

    u32 h2h[2][2], h2l[2][2];
    #pragma unroll
    for (int nb2 = 0; nb2 < 2; nb2++) {
        u64 u0 = fma2(fma2(pk2(d2f[nb2][0], d2f[nb2][1]), sc2pA, nm2pA), g2p[nb2], b2p[nb2]);
        u64 u1 = fma2(fma2(pk2(d2f[nb2][2], d2f[nb2][3]), sc2pB, nm2pB), g2p[nb2], b2p[nb2]);
        float2 f0 = upk2(u0), f1 = upk2(u1);
        split2(fmaxf(f0.x, 0.f), fmaxf(f0.y, 0.f), h2h[nb2][0], h2l[nb2][0]);
        split2(fmaxf(f1.x, 0.f), fmaxf(f1.y, 0.f), h2h[nb2][1], h2l[nb2][1]);
    }

    // ---- layer 3 on HMMA ----
    const uint4 w3q = sW3F[lane];
    float e0 = 0.f, e1 = 0.f, e2 = 0.f, e3 = 0.f;
    mma_bf16(e0,e1,e2,e3, h2h[0][0],h2h[0][1],h2h[1][0],h2h[1][1], w3q.x, w3q.y);
    mma_bf16(e0,e1,e2,e3, h2h[0][0],h2h[0][1],h2h[1][0],h2h[1][1], w3q.z, w3q.w);
    mma_bf16(e0,e1,e2,e3, h2l[0][0],h2l[0][1],h2l[1][0],h2l[1][1], w3q.x, w3q.y);

    // ---- gather channel 2 from quad neighbor, normalize (rsqrt, no div), store ----
    const float c2A = __shfl_down_sync(0xffffffffu, e0, 1);
    const float c2B = __shfl_down_sync(0xffffffffu, e2, 1);
    if (t == 0) {
        {
            const int row = R + g;
            if (row < N) {
                const float o0 = e0 + bb0, o1 = e1 + bb1, o2 = c2A + bb2;
                const float s   = o0*o0 + o1*o1 + o2*o2;
                const float inv = rsqrtf(fmaxf(s, 1e-24f));   // == 1/max(sqrt(s),1e-12)
                const int b  = row / HW;
                const int hw = row - b * HW;
                const int ob = (b * 3) * HW + hw;
                out[ob] = o0 * inv; out[ob + HW] = o1 * inv; out[ob + 2*HW] = o2 * inv;
            }
        }
        {
            const int row = R + g + 8;
            if (row < N) {
                const float o0 = e2 + bb0, o1 = e3 + bb1, o2 = c2B + bb2;
                const float s   = o0*o0 + o1*o1 + o2*o2;
                const float inv = rsqrtf(fmaxf(s, 1e-24f));
                const int b  = row / HW;
                const int hw = row - b * HW;
                const int ob = (b * 3) * HW + hw;
                out[ob] = o0 * inv; out[ob + HW] = o1 * inv; out[ob + 2*HW] = o2 * inv;
            }
        }
    }
}

__global__ __launch_bounds__(TPB, 4)
void fused_decoder_frag(const float* __restrict__ x,
                        const float* __restrict__ w1,
                        const float* __restrict__ g1v,
                        const float* __restrict__ b1v,
                        const float* __restrict__ w2,
                        const float* __restrict__ g2v,
                        const float* __restrict__ b2v,
                        const float* __restrict__ w3,
                        const float* __restrict__ b3,
                        const int*   __restrict__ Bp,
                        float*       __restrict__ out,
                        int N, int ngroups)
{
    // w1 B-fragments: ONE uint4 per (kn, lane) = {bh0, bh1, bl0, bl1} -> single LDS.128
    __shared__ __align__(16) uint4 sB[16][32];
    // per-lane constant fragment images
    __shared__ __align__(16) uint4      sW2H[2][32];
    __shared__ __align__(16) uint4      sW2L[2][32];
    __shared__ __align__(16) uint4      sW3F[32];
    __shared__ __align__(16) ulonglong2 sG1[2][32];
    __shared__ __align__(16) ulonglong2 sB1[2][32];
    __shared__ __align__(16) ulonglong2 sG2[32];
    __shared__ __align__(16) ulonglong2 sB2[32];
    __shared__ float sb3s[3];

    const int tid  = threadIdx.x;
    const int wid  = tid >> 5;
    const int lane = tid & 31;
    const int g    = lane >> 2;        // row-in-group 0..7
    const int t    = lane & 3;         // col-quad selector

    // ---- one-time: stage w1 B-frags with the k permutation baked in ----
    for (int e = tid; e < 512; e += TPB) {
        const int kn = e >> 5, l = e & 31;
        const int kb = kn >> 2, nb = kn & 3;
        const int c4 = (l & 3) * 4;
        const int gg = l >> 2;
        const int col  = nb * 8 + gg;
        const int krow = kb * 16 + c4;
        u32 h01, l01, h23, l23;
        split2(w1[(krow + 0) * 32 + col], w1[(krow + 1) * 32 + col], h01, l01);
        split2(w1[(krow + 2) * 32 + col], w1[(krow + 3) * 32 + col], h23, l23);
        sB[kn][l] = make_uint4(h01, h23, l01, l23);
    }

    // ---- one-time: per-lane constant images (warp 0 computes) ----
    if (wid == 0) {
        #pragma unroll
        for (int kb2 = 0; kb2 < 2; kb2++) {
            const int k0 = kb2 * 16 + 2 * t;
            u32 h00, l00, h01_, l01_, h10, l10, h11, l11;
            split2(w2[k0 * 16 + g],           w2[(k0 + 1) * 16 + g],           h00, l00);
            split2(w2[(k0 + 8) * 16 + g],     w2[(k0 + 9) * 16 + g],           h01_, l01_);
            split2(w2[k0 * 16 + 8 + g],       w2[(k0 + 1) * 16 + 8 + g],       h10, l10);
            split2(w2[(k0 + 8) * 16 + 8 + g], w2[(k0 + 9) * 16 + 8 + g],       h11, l11);
            sW2H[kb2][lane] = make_uint4(h00, h01_, h10, h11);
            sW2L[kb2][lane] = make_uint4(l00, l01_, l10, l11);
        }
        {
            u32 wh0 = 0u, wh1 = 0u, wl0 = 0u, wl1 = 0u;
            if (g < 3) {
                const int k0 = 2 * t;
                split2(w3[k0 * 3 + g],       w3[(k0 + 1) * 3 + g], wh0, wl0);
                split2(w3[(k0 + 8) * 3 + g], w3[(k0 + 9) * 3 + g], wh1, wl1);
            }
            sW3F[lane] = make_uint4(wh0, wh1, wl0, wl1);
        }
        {
            u64 gp[4], bp[4];
            #pragma unroll
            for (int nb = 0; nb < 4; nb++) {
                const int c0 = nb * 8 + 2 * t;
                gp[nb] = pk2(g1v[c0], g1v[c0 + 1]);
                bp[nb] = pk2(b1v[c0], b1v[c0 + 1]);
            }
            sG1[0][lane] = make_ulonglong2(gp[0], gp[1]);
            sG1[1][lane] = make_ulonglong2(gp[2], gp[3]);
            sB1[0][lane] = make_ulonglong2(bp[0], bp[1]);
            sB1[1][lane] = make_ulonglong2(bp[2], bp[3]);
            sG2[lane] = make_ulonglong2(pk2(g2v[2*t], g2v[2*t+1]), pk2(g2v[8+2*t], g2v[8+2*t+1]));
            sB2[lane] = make_ulonglong2(pk2(b2v[2*t], b2v[2*t+1]), pk2(b2v[8+2*t], b2v[8+2*t+1]));
        }
        if (lane < 3) sb3s[lane] = b3[lane];
    }
    __syncthreads();

    const int Bv = __ldg(Bp);
    const int HW = N / Bv;
    const float bb0 = sb3s[0], bb1 = sb3s[1], bb2 = sb3s[2];

    const int gw0    = blockIdx.x * 4 + wid;
    const int nwarps = gridDim.x * 4;

    int grp = gw0;
    if (grp >= ngroups) return;

    float4 q0[4], q1[4];
    load_x(x, grp * 16, g, t, N, q0, q1);

    // layer-1 step: split q -> frags, prefetch next q, run MMAs into d1o
    auto layer1_step = [&](float (*d1o)[4], int gcur) {
        u32 ah[4][4], al[4][4];
        #pragma unroll
        for (int kb = 0; kb < 4; kb++) {
            split2(q0[kb].x, q0[kb].y, ah[kb][0], al[kb][0]);
            split2(q1[kb].x, q1[kb].y, ah[kb][1], al[kb][1]);
            split2(q0[kb].z, q0[kb].w, ah[kb][2], al[kb][2]);
            split2(q1[kb].z, q1[kb].w, ah[kb][3], al[kb][3]);
        }
        const int nn = gcur + nwarps;
        if (nn < ngroups) load_x(x, nn * 16, g, t, N, q0, q1);
        #pragma unroll
        for (int nb = 0; nb < 4; nb++) {
            float d0 = 0.f, dd1 = 0.f, d2 = 0.f, d3 = 0.f;
            #pragma unroll
            for (int kb = 0; kb < 4; kb++) {
                const uint4 b = sB[kb * 4 + nb][lane];
                mma_bf16(d0,dd1,d2,d3, ah[kb][0],ah[kb][1],ah[kb][2],ah[kb][3], b.x, b.y);
                mma_bf16(d0,dd1,d2,d3, ah[kb][0],ah[kb][1],ah[kb][2],ah[kb][3], b.z, b.w);
                mma_bf16(d0,dd1,d2,d3, al[kb][0],al[kb][1],al[kb][2],al[kb][3], b.x, b.y);
            }
            d1o[nb][0] = d0; d1o[nb][1] = dd1; d1o[nb][2] = d2; d1o[nb][3] = d3;
        }
    };

    float dA[4][4], dB[4][4];
    int RA, RB;

    // prologue: layer-1 of first group into dA
    RA = grp * 16;
    layer1_step(dA, grp);
    grp += nwarps;

    // steady state, ping-pong: no d1 copy (epilogue(i-1) interleaves with layer1(i))
    #pragma unroll 1
    while (true) {
        if (grp >= ngroups) {
            epilogue(dA, RA, N, HW, lane, g, t, bb0, bb1, bb2,
                     &sG1[0][0], &sB1[0][0], &sW2H[0][0], &sW2L[0][0],
                     sW3F, sG2, sB2, out);
            break;
        }
        RB = grp * 16;
        layer1_step(dB, grp);
        epilogue(dA, RA, N, HW, lane, g, t, bb0, bb1, bb2,
                 &sG1[0][0], &sB1[0][0], &sW2H[0][0], &sW2L[0][0],
                 sW3F, sG2, sB2, out);
        grp += nwarps;

        if (grp >= ngroups) {
            epilogue(dB, RB, N, HW, lane, g, t, bb0, bb1, bb2,
                     &sG1[0][0], &sB1[0][0], &sW2H[0][0], &sW2L[0][0],
                     sW3F, sG2, sB2, out);
            break;
        }
        RA = grp * 16;
        layer1_step(dA, grp);
        epilogue(dB, RB, N, HW, lane, g, t, bb0, bb1, bb2,
                 &sG1[0][0], &sB1[0][0], &sW2H[0][0], &sW2L[0][0],
                 sW3F, sG2, sB2, out);
        grp += nwarps;
    }
}

extern "C" void kernel_launch(void* const* d_in, const int* in_sizes, int n_in,
                              void* d_out, int out_size)
{
    const float* x  = (const float*)d_in[0];
    const float* w1 = (const float*)d_in[1];
    const float* g1 = (const float*)d_in[2];
    const float* b1 = (const float*)d_in[3];
    const float* w2 = (const float*)d_in[4];
    const float* g2 = (const float*)d_in[5];
    const float* b2 = (const float*)d_in[6];
    const float* w3 = (const float*)d_in[7];
    const float* b3 = (const float*)d_in[8];
    const int*   Bp = (const int*)d_in[9];

    const int N       = in_sizes[0] / 64;
    const int ngroups = (N + 15) / 16;
    int blocks = (ngroups + 3) / 4;
    if (blocks > NCTAS) blocks = NCTAS;

    fused_decoder_frag<<<blocks, TPB>>>(
        x, w1, g1, b1, w2, g2, b2, w3, b3, Bp,
        (float*)d_out, N, ngroups);
}

// round 15
// speedup vs baseline: 1.4798x; 1.4798x over previous
#include <cuda_runtime.h>
#include <cuda_bf16.h>

typedef unsigned long long u64;
typedef unsigned int u32;

// ---------------- packed f32x2 helpers ----------------
__device__ __forceinline__ u64 pk2(float lo, float hi) {
    u64 r; asm("mov.b64 %0,{%1,%2};" : "=l"(r) : "f"(lo), "f"(hi)); return r;
}
__device__ __forceinline__ float2 upk2(u64 v) {
    float2 f; asm("mov.b64 {%0,%1},%2;" : "=f"(f.x), "=f"(f.y) : "l"(v)); return f;
}
__device__ __forceinline__ u64 fma2(u64 a, u64 b, u64 c) {
    u64 d; asm("fma.rn.f32x2 %0,%1,%2,%3;" : "=l"(d) : "l"(a), "l"(b), "l"(c)); return d;
}
__device__ __forceinline__ u64 add2(u64 a, u64 b) {
    u64 d; asm("add.rn.f32x2 %0,%1,%2;" : "=l"(d) : "l"(a), "l"(b)); return d;
}

// ---------------- HMMA m16n8k16 row.col f32.bf16.bf16.f32 ----------------
__device__ __forceinline__ void mma_bf16(float& d0, float& d1, float& d2, float& d3,
                                         u32 a0, u32 a1, u32 a2, u32 a3,
                                         u32 b0, u32 b1) {
    asm volatile(
        "mma.sync.aligned.m16n8k16.row.col.f32.bf16.bf16.f32 "
        "{%0,%1,%2,%3}, {%4,%5,%6,%7}, {%8,%9}, {%0,%1,%2,%3};"
        : "+f"(d0), "+f"(d1), "+f"(d2), "+f"(d3)
        : "r"(a0), "r"(a1), "r"(a2), "r"(a3), "r"(b0), "r"(b1));
}

// two floats -> bf16x2 hi + bf16x2 residual lo (bit-op reconstruction + packed fma)
__device__ __forceinline__ void split2(float v0, float v1, u32& h, u32& l) {
    __nv_bfloat162 hb = __float22bfloat162_rn(make_float2(v0, v1));
    h = *reinterpret_cast<u32*>(&hb);
    const float f0 = __uint_as_float(h << 16);
    const float f1 = __uint_as_float(h & 0xffff0000u);
    const u64 r = fma2(pk2(f0, f1), 0xBF800000BF800000ull /*(-1,-1)*/, pk2(v0, v1));
    const float2 rf = upk2(r);
    __nv_bfloat162 lb = __float22bfloat162_rn(make_float2(rf.x, rf.y));
    l = *reinterpret_cast<u32*>(&lb);
}

__device__ __forceinline__ u64 shflx(u64 v, int m) {
    return (u64)__shfl_xor_sync(0xffffffffu, (unsigned long long)v, m);
}

#define TPB    128
#define NCTAS  592   // 148 SM * 4

// raw x loads for one 16-row group (k-permuted: lane quad t reads cols [4t,4t+3])
__device__ __forceinline__ void load_x(const float* __restrict__ x, int R, int g, int t,
                                       int N, float4 q0[4], float4 q1[4]) {
    int r0 = R + g;     if (r0 > N - 1) r0 = N - 1;
    int r1 = R + g + 8; if (r1 > N - 1) r1 = N - 1;
    const float4* p0 = (const float4*)(x + (size_t)r0 * 64 + 4 * t);
    const float4* p1 = (const float4*)(x + (size_t)r1 * 64 + 4 * t);
    #pragma unroll
    for (int kb = 0; kb < 4; kb++) { q0[kb] = p0[kb * 4]; q1[kb] = p1[kb * 4]; }
}

// full epilogue for one 16-row group, operating on its layer-1 D fragments
__device__ __forceinline__ void epilogue(
    const float d1[4][4], int R, int N, int HW, int lane, int g, int t,
    float bb0, float bb1, float bb2,
    const ulonglong2* __restrict__ sG1, const ulonglong2* __restrict__ sB1,   // [2][32] flat
    const uint4* __restrict__ sW2H, const uint4* __restrict__ sW2L,           // [2][32] flat
    const uint4* __restrict__ sW3F,                                           // [32]
    const ulonglong2* __restrict__ sG2, const ulonglong2* __restrict__ sB2,   // [32]
    float* __restrict__ out)
{
    // ---- LN1 in frag layout: quad shuffle stats ----
    u64 ss = 0ull, qq = 0ull;
    #pragma unroll
    for (int nb = 0; nb < 4; nb++) {
        const u64 m0 = pk2(d1[nb][0], d1[nb][2]);
        const u64 m1 = pk2(d1[nb][1], d1[nb][3]);
        ss = add2(ss, add2(m0, m1));
        qq = fma2(m0, m0, fma2(m1, m1, qq));
    }
    ss = add2(ss, shflx(ss, 1)); ss = add2(ss, shflx(ss, 2));
    qq = add2(qq, shflx(qq, 1)); qq = add2(qq, shflx(qq, 2));
    float2 sv = upk2(ss), qv = upk2(qq);
    const float mgA = sv.x * (1.0f/32.0f), mgB = sv.y * (1.0f/32.0f);
    const float scA = rsqrtf(qv.x * (1.0f/32.0f) - mgA * mgA + 1e-5f);
    const float scB = rsqrtf(qv.y * (1.0f/32.0f) - mgB * mgB + 1e-5f);
    const u64 scpA = pk2(scA, scA), nmpA = pk2(-mgA*scA, -mgA*scA);
    const u64 scpB = pk2(scB, scB), nmpB = pk2(-mgB*scB, -mgB*scB);

    const ulonglong2 g1a = sG1[lane], g1b = sG1[32 + lane];
    const ulonglong2 b1a = sB1[lane], b1b = sB1[32 + lane];
    const u64 g1p[4] = {g1a.x, g1a.y, g1b.x, g1b.y};
    const u64 b1p[4] = {b1a.x, b1a.y, b1b.x, b1b.y};

    u32 hh[4][2], hl[4][2];
    #pragma unroll
    for (int nb = 0; nb < 4; nb++) {
        u64 u0 = fma2(fma2(pk2(d1[nb][0], d1[nb][1]), scpA, nmpA), g1p[nb], b1p[nb]);
        u64 u1 = fma2(fma2(pk2(d1[nb][2], d1[nb][3]), scpB, nmpB), g1p[nb], b1p[nb]);
        float2 f0 = upk2(u0), f1 = upk2(u1);
        split2(fmaxf(f0.x, 0.f), fmaxf(f0.y, 0.f), hh[nb][0], hl[nb][0]);
        split2(fmaxf(f1.x, 0.f), fmaxf(f1.y, 0.f), hh[nb][1], hl[nb][1]);
    }

    // ---- layer 2 on HMMA (w2 frags from smem) ----
    const uint4 w2h0 = sW2H[lane], w2h1 = sW2H[32 + lane];
    const uint4 w2l0 = sW2L[lane], w2l1 = sW2L[32 + lane];

    float d2f[2][4];
    {
        float d0 = 0.f, dd1 = 0.f, d2 = 0.f, d3 = 0.f;
        mma_bf16(d0,dd1,d2,d3, hh[0][0],hh[0][1],hh[1][0],hh[1][1], w2h0.x, w2h0.y);
        mma_bf16(d0,dd1,d2,d3, hh[0][0],hh[0][1],hh[1][0],hh[1][1], w2l0.x, w2l0.y);
        mma_bf16(d0,dd1,d2,d3, hl[0][0],hl[0][1],hl[1][0],hl[1][1], w2h0.x, w2h0.y);
        mma_bf16(d0,dd1,d2,d3, hh[2][0],hh[2][1],hh[3][0],hh[3][1], w2h1.x, w2h1.y);
        mma_bf16(d0,dd1,d2,d3, hh[2][0],hh[2][1],hh[3][0],hh[3][1], w2l1.x, w2l1.y);
        mma_bf16(d0,dd1,d2,d3, hl[2][0],hl[2][1],hl[3][0],hl[3][1], w2h1.x, w2h1.y);
        d2f[0][0] = d0; d2f[0][1] = dd1; d2f[0][2] = d2; d2f[0][3] = d3;
        d0 = 0.f; dd1 = 0.f; d2 = 0.f; d3 = 0.f;
        mma_bf16(d0,dd1,d2,d3, hh[0][0],hh[0][1],hh[1][0],hh[1][1], w2h0.z, w2h0.w);
        mma_bf16(d0,dd1,d2,d3, hh[0][0],hh[0][1],hh[1][0],hh[1][1], w2l0.z, w2l0.w);
        mma_bf16(d0,dd1,d2,d3, hl[0][0],hl[0][1],hl[1][0],hl[1][1], w2h0.z, w2h0.w);
        mma_bf16(d0,dd1,d2,d3, hh[2][0],hh[2][1],hh[3][0],hh[3][1], w2h1.z, w2h1.w);
        mma_bf16(d0,dd1,d2,d3, hh[2][0],hh[2][1],hh[3][0],hh[3][1], w2l1.z, w2l1.w);
        mma_bf16(d0,dd1,d2,d3, hl[2][0],hl[2][1],hl[3][0],hl[3][1], w2h1.z, w2h1.w);
        d2f[1][0] = d0; d2f[1][1] = dd1; d2f[1][2] = d2; d2f[1][3] = d3;
    }

    // ---- LN2 ----
    u64 ss2 = 0ull, qq2 = 0ull;
    #pragma unroll
    for (int nb2 = 0; nb2 < 2; nb2++) {
        const u64 m0 = pk2(d2f[nb2][0], d2f[nb2][2]);
        const u64 m1 = pk2(d2f[nb2][1], d2f[nb2][3]);
        ss2 = add2(ss2, add2(m0, m1));
        qq2 = fma2(m0, m0, fma2(m1, m1, qq2));
    }
    ss2 = add2(ss2, shflx(ss2, 1)); ss2 = add2(ss2, shflx(ss2, 2));
    qq2 = add2(qq2, shflx(qq2, 1)); qq2 = add2(qq2, shflx(qq2, 2));
    float2 sv2 = upk2(ss2), qv2 = upk2(qq2);
    const float m2A = sv2.x * (1.0f/16.0f), m2B = sv2.y * (1.0f/16.0f);
    const float s2A = rsqrtf(qv2.x * (1.0f/16.0f) - m2A * m2A + 1e-5f);
    const float s2B = rsqrtf(qv2.y * (1.0f/16.0f) - m2B * m2B + 1e-5f);
    const u64 sc2pA = pk2(s2A, s2A), nm2pA = pk2(-m2A*s2A, -m2A*s2A);
    const u64 sc2pB = pk2(s2B, s2B), nm2pB = pk2(-m2B*s2B, -m2B*s2B);

    const ulonglong2 g2q = sG2[lane], b2q = sB2[lane];
    const u64 g2p[2] = {g2q.x, g2q.y};
    const u64 b2p[2] = {b2q.x, b2q.y};

    u32 h2h[2][2], h2l[2][2];
    #pragma unroll
    for (int nb2 = 0; nb2 < 2; nb2++) {
        u64 u0 = fma2(fma2(pk2(d2f[nb2][0], d2f[nb2][1]), sc2pA, nm2pA), g2p[nb2], b2p[nb2]);
        u64 u1 = fma2(fma2(pk2(d2f[nb2][2], d2f[nb2][3]), sc2pB, nm2pB), g2p[nb2], b2p[nb2]);
        float2 f0 = upk2(u0), f1 = upk2(u1);
        split2(fmaxf(f0.x, 0.f), fmaxf(f0.y, 0.f), h2h[nb2][0], h2l[nb2][0]);
        split2(fmaxf(f1.x, 0.f), fmaxf(f1.y, 0.f), h2h[nb2][1], h2l[nb2][1]);
    }

    // ---- layer 3 on HMMA ----
    const uint4 w3q = sW3F[lane];
    float e0 = 0.f, e1 = 0.f, e2 = 0.f, e3 = 0.f;
    mma_bf16(e0,e1,e2,e3, h2h[0][0],h2h[0][1],h2h[1][0],h2h[1][1], w3q.x, w3q.y);
    mma_bf16(e0,e1,e2,e3, h2h[0][0],h2h[0][1],h2h[1][0],h2h[1][1], w3q.z, w3q.w);
    mma_bf16(e0,e1,e2,e3, h2l[0][0],h2l[0][1],h2l[1][0],h2l[1][1], w3q.x, w3q.y);

    // ---- gather channel 2 from quad neighbor, normalize (rsqrt, no div), store ----
    const float c2A = __shfl_down_sync(0xffffffffu, e0, 1);
    const float c2B = __shfl_down_sync(0xffffffffu, e2, 1);
    if (t == 0) {
        {
            const int row = R + g;
            if (row < N) {
                const float o0 = e0 + bb0, o1 = e1 + bb1, o2 = c2A + bb2;
                const float s   = o0*o0 + o1*o1 + o2*o2;
                const float inv = rsqrtf(fmaxf(s, 1e-24f));   // == 1/max(sqrt(s),1e-12)
                const int b  = row / HW;
                const int hw = row - b * HW;
                const int ob = (b * 3) * HW + hw;
                out[ob] = o0 * inv; out[ob + HW] = o1 * inv; out[ob + 2*HW] = o2 * inv;
            }
        }
        {
            const int row = R + g + 8;
            if (row < N) {
                const float o0 = e2 + bb0, o1 = e3 + bb1, o2 = c2B + bb2;
                const float s   = o0*o0 + o1*o1 + o2*o2;
                const float inv = rsqrtf(fmaxf(s, 1e-24f));
                const int b  = row / HW;
                const int hw = row - b * HW;
                const int ob = (b * 3) * HW + hw;
                out[ob] = o0 * inv; out[ob + HW] = o1 * inv; out[ob + 2*HW] = o2 * inv;
            }
        }
    }
}

__global__ __launch_bounds__(TPB, 4)
void fused_decoder_frag(const float* __restrict__ x,
                        const float* __restrict__ w1,
                        const float* __restrict__ g1v,
                        const float* __restrict__ b1v,
                        const float* __restrict__ w2,
                        const float* __restrict__ g2v,
                        const float* __restrict__ b2v,
                        const float* __restrict__ w3,
                        const float* __restrict__ b3,
                        const int*   __restrict__ Bp,
                        float*       __restrict__ out,
                        int N, int ngroups)
{
    // w1 B-fragments: ONE uint4 per (kn, lane) = {bh0, bh1, bl0, bl1} -> single LDS.128
    __shared__ __align__(16) uint4 sB[16][32];
    // per-lane constant fragment images
    __shared__ __align__(16) uint4      sW2H[2][32];
    __shared__ __align__(16) uint4      sW2L[2][32];
    __shared__ __align__(16) uint4      sW3F[32];
    __shared__ __align__(16) ulonglong2 sG1[2][32];
    __shared__ __align__(16) ulonglong2 sB1[2][32];
    __shared__ __align__(16) ulonglong2 sG2[32];
    __shared__ __align__(16) ulonglong2 sB2[32];
    __shared__ float sb3s[3];

    const int tid  = threadIdx.x;
    const int wid  = tid >> 5;
    const int lane = tid & 31;
    const int g    = lane >> 2;        // row-in-group 0..7
    const int t    = lane & 3;         // col-quad selector

    // ---- one-time: stage w1 B-frags with the k permutation baked in ----
    for (int e = tid; e < 512; e += TPB) {
        const int kn = e >> 5, l = e & 31;
        const int kb = kn >> 2, nb = kn & 3;
        const int c4 = (l & 3) * 4;
        const int gg = l >> 2;
        const int col  = nb * 8 + gg;
        const int krow = kb * 16 + c4;
        u32 h01, l01, h23, l23;
        split2(w1[(krow + 0) * 32 + col], w1[(krow + 1) * 32 + col], h01, l01);
        split2(w1[(krow + 2) * 32 + col], w1[(krow + 3) * 32 + col], h23, l23);
        sB[kn][l] = make_uint4(h01, h23, l01, l23);
    }

    // ---- one-time: per-lane constant images (warp 0 computes) ----
    if (wid == 0) {
        #pragma unroll
        for (int kb2 = 0; kb2 < 2; kb2++) {
            const int k0 = kb2 * 16 + 2 * t;
            u32 h00, l00, h01_, l01_, h10, l10, h11, l11;
            split2(w2[k0 * 16 + g],           w2[(k0 + 1) * 16 + g],           h00, l00);
            split2(w2[(k0 + 8) * 16 + g],     w2[(k0 + 9) * 16 + g],           h01_, l01_);
            split2(w2[k0 * 16 + 8 + g],       w2[(k0 + 1) * 16 + 8 + g],       h10, l10);
            split2(w2[(k0 + 8) * 16 + 8 + g], w2[(k0 + 9) * 16 + 8 + g],       h11, l11);
            sW2H[kb2][lane] = make_uint4(h00, h01_, h10, h11);
            sW2L[kb2][lane] = make_uint4(l00, l01_, l10, l11);
        }
        {
            u32 wh0 = 0u, wh1 = 0u, wl0 = 0u, wl1 = 0u;
            if (g < 3) {
                const int k0 = 2 * t;
                split2(w3[k0 * 3 + g],       w3[(k0 + 1) * 3 + g], wh0, wl0);
                split2(w3[(k0 + 8) * 3 + g], w3[(k0 + 9) * 3 + g], wh1, wl1);
            }
            sW3F[lane] = make_uint4(wh0, wh1, wl0, wl1);
        }
        {
            u64 gp[4], bp[4];
            #pragma unroll
            for (int nb = 0; nb < 4; nb++) {
                const int c0 = nb * 8 + 2 * t;
                gp[nb] = pk2(g1v[c0], g1v[c0 + 1]);
                bp[nb] = pk2(b1v[c0], b1v[c0 + 1]);
            }
            sG1[0][lane] = make_ulonglong2(gp[0], gp[1]);
            sG1[1][lane] = make_ulonglong2(gp[2], gp[3]);
            sB1[0][lane] = make_ulonglong2(bp[0], bp[1]);
            sB1[1][lane] = make_ulonglong2(bp[2], bp[3]);
            sG2[lane] = make_ulonglong2(pk2(g2v[2*t], g2v[2*t+1]), pk2(g2v[8+2*t], g2v[8+2*t+1]));
            sB2[lane] = make_ulonglong2(pk2(b2v[2*t], b2v[2*t+1]), pk2(b2v[8+2*t], b2v[8+2*t+1]));
        }
        if (lane < 3) sb3s[lane] = b3[lane];
    }
    __syncthreads();

    const int Bv = __ldg(Bp);
    const int HW = N / Bv;
    const float bb0 = sb3s[0], bb1 = sb3s[1], bb2 = sb3s[2];

    const int gw0    = blockIdx.x * 4 + wid;
    const int nwarps = gridDim.x * 4;

    int grp = gw0;
    if (grp >= ngroups) return;

    float4 q0[4], q1[4];
    load_x(x, grp * 16, g, t, N, q0, q1);

    // ---- prologue: layer-1 for the first group ----
    float d1p[4][4];
    int   Rp = grp * 16;
    {
        u32 ah[4][4], al[4][4];
        #pragma unroll
        for (int kb = 0; kb < 4; kb++) {
            split2(q0[kb].x, q0[kb].y, ah[kb][0], al[kb][0]);
            split2(q1[kb].x, q1[kb].y, ah[kb][1], al[kb][1]);
            split2(q0[kb].z, q0[kb].w, ah[kb][2], al[kb][2]);
            split2(q1[kb].z, q1[kb].w, ah[kb][3], al[kb][3]);
        }
        const int nxt = grp + nwarps;
        if (nxt < ngroups) load_x(x, nxt * 16, g, t, N, q0, q1);
        #pragma unroll
        for (int nb = 0; nb < 4; nb++) {
            float d0 = 0.f, dd1 = 0.f, d2 = 0.f, d3 = 0.f;
            #pragma unroll
            for (int kb = 0; kb < 4; kb++) {
                const uint4 b = sB[kb * 4 + nb][lane];
                mma_bf16(d0,dd1,d2,d3, ah[kb][0],ah[kb][1],ah[kb][2],ah[kb][3], b.x, b.y);
                mma_bf16(d0,dd1,d2,d3, ah[kb][0],ah[kb][1],ah[kb][2],ah[kb][3], b.z, b.w);
                mma_bf16(d0,dd1,d2,d3, al[kb][0],al[kb][1],al[kb][2],al[kb][3], b.x, b.y);
            }
            d1p[nb][0] = d0; d1p[nb][1] = dd1; d1p[nb][2] = d2; d1p[nb][3] = d3;
        }
        grp = nxt;
    }

    // ---- steady state: layer-1(group i) interleaves with epilogue(group i-1) ----
    #pragma unroll 1
    while (grp < ngroups) {
        const int nxt = grp + nwarps;

        u32 ah[4][4], al[4][4];
        #pragma unroll
        for (int kb = 0; kb < 4; kb++) {
            split2(q0[kb].x, q0[kb].y, ah[kb][0], al[kb][0]);
            split2(q1[kb].x, q1[kb].y, ah[kb][1], al[kb][1]);
            split2(q0[kb].z, q0[kb].w, ah[kb][2], al[kb][2]);
            split2(q1[kb].z, q1[kb].w, ah[kb][3], al[kb][3]);
        }
        if (nxt < ngroups) load_x(x, nxt * 16, g, t, N, q0, q1);

        float d1n[4][4];
        #pragma unroll
        for (int nb = 0; nb < 4; nb++) {
            float d0 = 0.f, dd1 = 0.f, d2 = 0.f, d3 = 0.f;
            #pragma unroll
            for (int kb = 0; kb < 4; kb++) {
                const uint4 b = sB[kb * 4 + nb][lane];
                mma_bf16(d0,dd1,d2,d3, ah[kb][0],ah[kb][1],ah[kb][2],ah[kb][3], b.x, b.y);
                mma_bf16(d0,dd1,d2,d3, ah[kb][0],ah[kb][1],ah[kb][2],ah[kb][3], b.z, b.w);
                mma_bf16(d0,dd1,d2,d3, al[kb][0],al[kb][1],al[kb][2],al[kb][3], b.x, b.y);
            }
            d1n[nb][0] = d0; d1n[nb][1] = dd1; d1n[nb][2] = d2; d1n[nb][3] = d3;
        }

        // epilogue for the PREVIOUS group (independent of d1n -> scheduler interleaves)
        epilogue(d1p, Rp, N, HW, lane, g, t, bb0, bb1, bb2,
                 &sG1[0][0], &sB1[0][0], &sW2H[0][0], &sW2L[0][0],
                 sW3F, sG2, sB2, out);

        #pragma unroll
        for (int nb = 0; nb < 4; nb++)
            #pragma unroll
            for (int j = 0; j < 4; j++) d1p[nb][j] = d1n[nb][j];
        Rp  = grp * 16;
        grp = nxt;
    }

    // ---- drain: epilogue for the final group ----
    epilogue(d1p, Rp, N, HW, lane, g, t, bb0, bb1, bb2,
             &sG1[0][0], &sB1[0][0], &sW2H[0][0], &sW2L[0][0],
             sW3F, sG2, sB2, out);
}

extern "C" void kernel_launch(void* const* d_in, const int* in_sizes, int n_in,
                              void* d_out, int out_size)
{
    const float* x  = (const float*)d_in[0];
    const float* w1 = (const float*)d_in[1];
    const float* g1 = (const float*)d_in[2];
    const float* b1 = (const float*)d_in[3];
    const float* w2 = (const float*)d_in[4];
    const float* g2 = (const float*)d_in[5];
    const float* b2 = (const float*)d_in[6];
    const float* w3 = (const float*)d_in[7];
    const float* b3 = (const float*)d_in[8];
    const int*   Bp = (const int*)d_in[9];

    const int N       = in_sizes[0] / 64;
    const int ngroups = (N + 15) / 16;
    int blocks = (ngroups + 3) / 4;
    if (blocks > NCTAS) blocks = NCTAS;

    fused_decoder_frag<<<blocks, TPB>>>(
        x, w1, g1, b1, w2, g2, b2, w3, b3, Bp,
        (float*)d_out, N, ngroups);
}

// round 16
// speedup vs baseline: 1.5450x; 1.0440x over previous
#include <cuda_runtime.h>
#include <cuda_bf16.h>

typedef unsigned long long u64;
typedef unsigned int u32;

// ---------------- packed f32x2 helpers ----------------
__device__ __forceinline__ u64 pk2(float lo, float hi) {
    u64 r; asm("mov.b64 %0,{%1,%2};" : "=l"(r) : "f"(lo), "f"(hi)); return r;
}
__device__ __forceinline__ float2 upk2(u64 v) {
    float2 f; asm("mov.b64 {%0,%1},%2;" : "=f"(f.x), "=f"(f.y) : "l"(v)); return f;
}
__device__ __forceinline__ u64 fma2(u64 a, u64 b, u64 c) {
    u64 d; asm("fma.rn.f32x2 %0,%1,%2,%3;" : "=l"(d) : "l"(a), "l"(b), "l"(c)); return d;
}
__device__ __forceinline__ u64 add2(u64 a, u64 b) {
    u64 d; asm("add.rn.f32x2 %0,%1,%2;" : "=l"(d) : "l"(a), "l"(b)); return d;
}

// ---------------- HMMA m16n8k16 row.col f32.bf16.bf16.f32 ----------------
__device__ __forceinline__ void mma_bf16(float& d0, float& d1, float& d2, float& d3,
                                         u32 a0, u32 a1, u32 a2, u32 a3,
                                         u32 b0, u32 b1) {
    asm volatile(
        "mma.sync.aligned.m16n8k16.row.col.f32.bf16.bf16.f32 "
        "{%0,%1,%2,%3}, {%4,%5,%6,%7}, {%8,%9}, {%0,%1,%2,%3};"
        : "+f"(d0), "+f"(d1), "+f"(d2), "+f"(d3)
        : "r"(a0), "r"(a1), "r"(a2), "r"(a3), "r"(b0), "r"(b1));
}

// two floats -> bf16x2 hi + bf16x2 residual lo (bit-op reconstruction + packed fma)
__device__ __forceinline__ void split2(float v0, float v1, u32& h, u32& l) {
    __nv_bfloat162 hb = __float22bfloat162_rn(make_float2(v0, v1));
    h = *reinterpret_cast<u32*>(&hb);
    const float f0 = __uint_as_float(h << 16);
    const float f1 = __uint_as_float(h & 0xffff0000u);
    const u64 r = fma2(pk2(f0, f1), 0xBF800000BF800000ull /*(-1,-1)*/, pk2(v0, v1));
    const float2 rf = upk2(r);
    __nv_bfloat162 lb = __float22bfloat162_rn(make_float2(rf.x, rf.y));
    l = *reinterpret_cast<u32*>(&lb);
}

__device__ __forceinline__ u64 shflx(u64 v, int m) {
    return (u64)__shfl_xor_sync(0xffffffffu, (unsigned long long)v, m);
}

#define TPB    128
#define NCTAS  592   // 148 SM * 4

// raw x loads for one 16-row group (k-permuted: lane quad t reads cols [4t,4t+3])
__device__ __forceinline__ void load_x(const float* __restrict__ x, int R, int g, int t,
                                       int N, float4 q0[4], float4 q1[4]) {
    int r0 = R + g;     if (r0 > N - 1) r0 = N - 1;
    int r1 = R + g + 8; if (r1 > N - 1) r1 = N - 1;
    const float4* p0 = (const float4*)(x + (size_t)r0 * 64 + 4 * t);
    const float4* p1 = (const float4*)(x + (size_t)r1 * 64 + 4 * t);
    #pragma unroll
    for (int kb = 0; kb < 4; kb++) { q0[kb] = p0[kb * 4]; q1[kb] = p1[kb * 4]; }
}

// full epilogue for one 16-row group, operating on its layer-1 D fragments
__device__ __forceinline__ void epilogue(
    const float d1[4][4], int R, int N, int HW, float invHW,
    int lane, int g, int t,
    float bb0, float bb1, float bb2,
    const ulonglong2* __restrict__ sG1, const ulonglong2* __restrict__ sB1,   // [2][32] flat
    const uint4* __restrict__ sW2H, const uint4* __restrict__ sW2L,           // [2][32] flat
    const uint4* __restrict__ sW3F,                                           // [32]
    const ulonglong2* __restrict__ sG2, const ulonglong2* __restrict__ sB2,   // [32]
    float* __restrict__ out)
{
    // ---- LN1 in frag layout: quad shuffle stats ----
    u64 ss = 0ull, qq = 0ull;
    #pragma unroll
    for (int nb = 0; nb < 4; nb++) {
        const u64 m0 = pk2(d1[nb][0], d1[nb][2]);
        const u64 m1 = pk2(d1[nb][1], d1[nb][3]);
        ss = add2(ss, add2(m0, m1));
        qq = fma2(m0, m0, fma2(m1, m1, qq));
    }
    ss = add2(ss, shflx(ss, 1)); ss = add2(ss, shflx(ss, 2));
    qq = add2(qq, shflx(qq, 1)); qq = add2(qq, shflx(qq, 2));
    float2 sv = upk2(ss), qv = upk2(qq);
    const float mgA = sv.x * (1.0f/32.0f), mgB = sv.y * (1.0f/32.0f);
    const float scA = rsqrtf(qv.x * (1.0f/32.0f) - mgA * mgA + 1e-5f);
    const float scB = rsqrtf(qv.y * (1.0f/32.0f) - mgB * mgB + 1e-5f);
    const u64 scpA = pk2(scA, scA), nmpA = pk2(-mgA*scA, -mgA*scA);
    const u64 scpB = pk2(scB, scB), nmpB = pk2(-mgB*scB, -mgB*scB);

    const ulonglong2 g1a = sG1[lane], g1b = sG1[32 + lane];
    const ulonglong2 b1a = sB1[lane], b1b = sB1[32 + lane];
    const u64 g1p[4] = {g1a.x, g1a.y, g1b.x, g1b.y};
    const u64 b1p[4] = {b1a.x, b1a.y, b1b.x, b1b.y};

    u32 hh[4][2], hl[4][2];
    #pragma unroll
    for (int nb = 0; nb < 4; nb++) {
        u64 u0 = fma2(fma2(pk2(d1[nb][0], d1[nb][1]), scpA, nmpA), g1p[nb], b1p[nb]);
        u64 u1 = fma2(fma2(pk2(d1[nb][2], d1[nb][3]), scpB, nmpB), g1p[nb], b1p[nb]);
        float2 f0 = upk2(u0), f1 = upk2(u1);
        split2(fmaxf(f0.x, 0.f), fmaxf(f0.y, 0.f), hh[nb][0], hl[nb][0]);
        split2(fmaxf(f1.x, 0.f), fmaxf(f1.y, 0.f), hh[nb][1], hl[nb][1]);
    }

    // ---- layer 2 on HMMA (w2 frags from smem) ----
    const uint4 w2h0 = sW2H[lane], w2h1 = sW2H[32 + lane];
    const uint4 w2l0 = sW2L[lane], w2l1 = sW2L[32 + lane];

    float d2f[2][4];
    {
        float d0 = 0.f, dd1 = 0.f, d2 = 0.f, d3 = 0.f;
        mma_bf16(d0,dd1,d2,d3, hh[0][0],hh[0][1],hh[1][0],hh[1][1], w2h0.x, w2h0.y);
        mma_bf16(d0,dd1,d2,d3, hh[0][0],hh[0][1],hh[1][0],hh[1][1], w2l0.x, w2l0.y);
        mma_bf16(d0,dd1,d2,d3, hl[0][0],hl[0][1],hl[1][0],hl[1][1], w2h0.x, w2h0.y);
        mma_bf16(d0,dd1,d2,d3, hh[2][0],hh[2][1],hh[3][0],hh[3][1], w2h1.x, w2h1.y);
        mma_bf16(d0,dd1,d2,d3, hh[2][0],hh[2][1],hh[3][0],hh[3][1], w2l1.x, w2l1.y);
        mma_bf16(d0,dd1,d2,d3, hl[2][0],hl[2][1],hl[3][0],hl[3][1], w2h1.x, w2h1.y);
        d2f[0][0] = d0; d2f[0][1] = dd1; d2f[0][2] = d2; d2f[0][3] = d3;
        d0 = 0.f; dd1 = 0.f; d2 = 0.f; d3 = 0.f;
        mma_bf16(d0,dd1,d2,d3, hh[0][0],hh[0][1],hh[1][0],hh[1][1], w2h0.z, w2h0.w);
        mma_bf16(d0,dd1,d2,d3, hh[0][0],hh[0][1],hh[1][0],hh[1][1], w2l0.z, w2l0.w);
        mma_bf16(d0,dd1,d2,d3, hl[0][0],hl[0][1],hl[1][0],hl[1][1], w2h0.z, w2h0.w);
        mma_bf16(d0,dd1,d2,d3, hh[2][0],hh[2][1],hh[3][0],hh[3][1], w2h1.z, w2h1.w);
        mma_bf16(d0,dd1,d2,d3, hh[2][0],hh[2][1],hh[3][0],hh[3][1], w2l1.z, w2l1.w);
        mma_bf16(d0,dd1,d2,d3, hl[2][0],hl[2][1],hl[3][0],hl[3][1], w2h1.z, w2h1.w);
        d2f[1][0] = d0; d2f[1][1] = dd1; d2f[1][2] = d2; d2f[1][3] = d3;
    }

    // ---- LN2 ----
    u64 ss2 = 0ull, qq2 = 0ull;
    #pragma unroll
    for (int nb2 = 0; nb2 < 2; nb2++) {
        const u64 m0 = pk2(d2f[nb2][0], d2f[nb2][2]);
        const u64 m1 = pk2(d2f[nb2][1], d2f[nb2][3]);
        ss2 = add2(ss2, add2(m0, m1));
        qq2 = fma2(m0, m0, fma2(m1, m1, qq2));
    }
    ss2 = add2(ss2, shflx(ss2, 1)); ss2 = add2(ss2, shflx(ss2, 2));
    qq2 = add2(qq2, shflx(qq2, 1)); qq2 = add2(qq2, shflx(qq2, 2));
    float2 sv2 = upk2(ss2), qv2 = upk2(qq2);
    const float m2A = sv2.x * (1.0f/16.0f), m2B = sv2.y * (1.0f/16.0f);
    const float s2A = rsqrtf(qv2.x * (1.0f/16.0f) - m2A * m2A + 1e-5f);
    const float s2B = rsqrtf(qv2.y * (1.0f/16.0f) - m2B * m2B + 1e-5f);
    const u64 sc2pA = pk2(s2A, s2A), nm2pA = pk2(-m2A*s2A, -m2A*s2A);
    const u64 sc2pB = pk2(s2B, s2B), nm2pB = pk2(-m2B*s2B, -m2B*s2B);

    const ulonglong2 g2q = sG2[lane], b2q = sB2[lane];
    const u64 g2p[2] = {g2q.x, g2q.y};
    const u64 b2p[2] = {b2q.x, b2q.y};

    u32 h2h[2][2], h2l[2][2];
    #pragma unroll
    for (int nb2 = 0; nb2 < 2; nb2++) {
        u64 u0 = fma2(fma2(pk2(d2f[nb2][0], d2f[nb2][1]), sc2pA, nm2pA), g2p[nb2], b2p[nb2]);
        u64 u1 = fma2(fma2(pk2(d2f[nb2][2], d2f[nb2][3]), sc2pB, nm2pB), g2p[nb2], b2p[nb2]);
        float2 f0 = upk2(u0), f1 = upk2(u1);
        split2(fmaxf(f0.x, 0.f), fmaxf(f0.y, 0.f), h2h[nb2][0], h2l[nb2][0]);
        split2(fmaxf(f1.x, 0.f), fmaxf(f1.y, 0.f), h2h[nb2][1], h2l[nb2][1]);
    }

    // ---- layer 3 on HMMA ----
    const uint4 w3q = sW3F[lane];
    float e0 = 0.f, e1 = 0.f, e2 = 0.f, e3 = 0.f;
    mma_bf16(e0,e1,e2,e3, h2h[0][0],h2h[0][1],h2h[1][0],h2h[1][1], w3q.x, w3q.y);
    mma_bf16(e0,e1,e2,e3, h2h[0][0],h2h[0][1],h2h[1][0],h2h[1][1], w3q.z, w3q.w);
    mma_bf16(e0,e1,e2,e3, h2l[0][0],h2l[0][1],h2l[1][0],h2l[1][1], w3q.x, w3q.y);

    // ---- gather channel 2 from quad neighbor, normalize (rsqrt), store ----
    const float c2A = __shfl_down_sync(0xffffffffu, e0, 1);
    const float c2B = __shfl_down_sync(0xffffffffu, e2, 1);
    if (t == 0) {
        {
            const int row = R + g;
            if (row < N) {
                const float o0 = e0 + bb0, o1 = e1 + bb1, o2 = c2A + bb2;
                const float s   = o0*o0 + o1*o1 + o2*o2;
                const float inv = rsqrtf(fmaxf(s, 1e-24f));
                // exact div-free b = row / HW (margin 0.5/HW >> float error)
                const int b  = (int)(((float)row + 0.5f) * invHW);
                const int hw = row - b * HW;
                const int ob = (b * 3) * HW + hw;
                out[ob] = o0 * inv; out[ob + HW] = o1 * inv; out[ob + 2*HW] = o2 * inv;
            }
        }
        {
            const int row = R + g + 8;
            if (row < N) {
                const float o0 = e2 + bb0, o1 = e3 + bb1, o2 = c2B + bb2;
                const float s   = o0*o0 + o1*o1 + o2*o2;
                const float inv = rsqrtf(fmaxf(s, 1e-24f));
                const int b  = (int)(((float)row + 0.5f) * invHW);
                const int hw = row - b * HW;
                const int ob = (b * 3) * HW + hw;
                out[ob] = o0 * inv; out[ob + HW] = o1 * inv; out[ob + 2*HW] = o2 * inv;
            }
        }
    }
}

__global__ __launch_bounds__(TPB, 4)
void fused_decoder_frag(const float* __restrict__ x,
                        const float* __restrict__ w1,
                        const float* __restrict__ g1v,
                        const float* __restrict__ b1v,
                        const float* __restrict__ w2,
                        const float* __restrict__ g2v,
                        const float* __restrict__ b2v,
                        const float* __restrict__ w3,
                        const float* __restrict__ b3,
                        const int*   __restrict__ Bp,
                        float*       __restrict__ out,
                        int N, int ngroups)
{
    // w1 B-fragments: ONE uint4 per (kn, lane) = {bh0, bh1, bl0, bl1} -> single LDS.128
    __shared__ __align__(16) uint4 sB[16][32];
    // per-lane constant fragment images
    __shared__ __align__(16) uint4      sW2H[2][32];
    __shared__ __align__(16) uint4      sW2L[2][32];
    __shared__ __align__(16) uint4      sW3F[32];
    __shared__ __align__(16) ulonglong2 sG1[2][32];
    __shared__ __align__(16) ulonglong2 sB1[2][32];
    __shared__ __align__(16) ulonglong2 sG2[32];
    __shared__ __align__(16) ulonglong2 sB2[32];
    __shared__ float sb3s[3];

    const int tid  = threadIdx.x;
    const int wid  = tid >> 5;
    const int lane = tid & 31;
    const int g    = lane >> 2;        // row-in-group 0..7
    const int t    = lane & 3;         // col-quad selector

    // ---- one-time: stage w1 B-frags with the k permutation baked in ----
    for (int e = tid; e < 512; e += TPB) {
        const int kn = e >> 5, l = e & 31;
        const int kb = kn >> 2, nb = kn & 3;
        const int c4 = (l & 3) * 4;
        const int gg = l >> 2;
        const int col  = nb * 8 + gg;
        const int krow = kb * 16 + c4;
        u32 h01, l01, h23, l23;
        split2(w1[(krow + 0) * 32 + col], w1[(krow + 1) * 32 + col], h01, l01);
        split2(w1[(krow + 2) * 32 + col], w1[(krow + 3) * 32 + col], h23, l23);
        sB[kn][l] = make_uint4(h01, h23, l01, l23);
    }

    // ---- one-time: per-lane constant images (warp 0 computes) ----
    if (wid == 0) {
        #pragma unroll
        for (int kb2 = 0; kb2 < 2; kb2++) {
            const int k0 = kb2 * 16 + 2 * t;
            u32 h00, l00, h01_, l01_, h10, l10, h11, l11;
            split2(w2[k0 * 16 + g],           w2[(k0 + 1) * 16 + g],           h00, l00);
            split2(w2[(k0 + 8) * 16 + g],     w2[(k0 + 9) * 16 + g],           h01_, l01_);
            split2(w2[k0 * 16 + 8 + g],       w2[(k0 + 1) * 16 + 8 + g],       h10, l10);
            split2(w2[(k0 + 8) * 16 + 8 + g], w2[(k0 + 9) * 16 + 8 + g],       h11, l11);
            sW2H[kb2][lane] = make_uint4(h00, h01_, h10, h11);
            sW2L[kb2][lane] = make_uint4(l00, l01_, l10, l11);
        }
        {
            u32 wh0 = 0u, wh1 = 0u, wl0 = 0u, wl1 = 0u;
            if (g < 3) {
                const int k0 = 2 * t;
                split2(w3[k0 * 3 + g],       w3[(k0 + 1) * 3 + g], wh0, wl0);
                split2(w3[(k0 + 8) * 3 + g], w3[(k0 + 9) * 3 + g], wh1, wl1);
            }
            sW3F[lane] = make_uint4(wh0, wh1, wl0, wl1);
        }
        {
            u64 gp[4], bp[4];
            #pragma unroll
            for (int nb = 0; nb < 4; nb++) {
                const int c0 = nb * 8 + 2 * t;
                gp[nb] = pk2(g1v[c0], g1v[c0 + 1]);
                bp[nb] = pk2(b1v[c0], b1v[c0 + 1]);
            }
            sG1[0][lane] = make_ulonglong2(gp[0], gp[1]);
            sG1[1][lane] = make_ulonglong2(gp[2], gp[3]);
            sB1[0][lane] = make_ulonglong2(bp[0], bp[1]);
            sB1[1][lane] = make_ulonglong2(bp[2], bp[3]);
            sG2[lane] = make_ulonglong2(pk2(g2v[2*t], g2v[2*t+1]), pk2(g2v[8+2*t], g2v[8+2*t+1]));
            sB2[lane] = make_ulonglong2(pk2(b2v[2*t], b2v[2*t+1]), pk2(b2v[8+2*t], b2v[8+2*t+1]));
        }
        if (lane < 3) sb3s[lane] = b3[lane];
    }
    __syncthreads();

    const int Bv = __ldg(Bp);
    const int HW = N / Bv;
    const float invHW = 1.0f / (float)HW;
    const float bb0 = sb3s[0], bb1 = sb3s[1], bb2 = sb3s[2];

    const int gw0    = blockIdx.x * 4 + wid;
    const int nwarps = gridDim.x * 4;

    int grp = gw0;
    if (grp >= ngroups) return;

    float4 q0[4], q1[4];
    load_x(x, grp * 16, g, t, N, q0, q1);

    // ---- prologue: layer-1 for the first group ----
    float d1p[4][4];
    int   Rp = grp * 16;
    {
        u32 ah[4][4], al[4][4];
        #pragma unroll
        for (int kb = 0; kb < 4; kb++) {
            split2(q0[kb].x, q0[kb].y, ah[kb][0], al[kb][0]);
            split2(q1[kb].x, q1[kb].y, ah[kb][1], al[kb][1]);
            split2(q0[kb].z, q0[kb].w, ah[kb][2], al[kb][2]);
            split2(q1[kb].z, q1[kb].w, ah[kb][3], al[kb][3]);
        }
        const int nxt = grp + nwarps;
        if (nxt < ngroups) load_x(x, nxt * 16, g, t, N, q0, q1);
        #pragma unroll
        for (int nb = 0; nb < 4; nb++) {
            float d0 = 0.f, dd1 = 0.f, d2 = 0.f, d3 = 0.f;
            #pragma unroll
            for (int kb = 0; kb < 4; kb++) {
                const uint4 b = sB[kb * 4 + nb][lane];
                mma_bf16(d0,dd1,d2,d3, ah[kb][0],ah[kb][1],ah[kb][2],ah[kb][3], b.x, b.y);
                mma_bf16(d0,dd1,d2,d3, ah[kb][0],ah[kb][1],ah[kb][2],ah[kb][3], b.z, b.w);
                mma_bf16(d0,dd1,d2,d3, al[kb][0],al[kb][1],al[kb][2],al[kb][3], b.x, b.y);
            }
            d1p[nb][0] = d0; d1p[nb][1] = dd1; d1p[nb][2] = d2; d1p[nb][3] = d3;
        }
        grp = nxt;
    }

    // ---- steady state: layer-1(group i) interleaves with epilogue(group i-1) ----
    #pragma unroll 1
    while (grp < ngroups) {
        const int nxt = grp + nwarps;

        u32 ah[4][4], al[4][4];
        #pragma unroll
        for (int kb = 0; kb < 4; kb++) {
            split2(q0[kb].x, q0[kb].y, ah[kb][0], al[kb][0]);
            split2(q1[kb].x, q1[kb].y, ah[kb][1], al[kb][1]);
            split2(q0[kb].z, q0[kb].w, ah[kb][2], al[kb][2]);
            split2(q1[kb].z, q1[kb].w, ah[kb][3], al[kb][3]);
        }
        if (nxt < ngroups) load_x(x, nxt * 16, g, t, N, q0, q1);

        float d1n[4][4];
        #pragma unroll
        for (int nb = 0; nb < 4; nb++) {
            float d0 = 0.f, dd1 = 0.f, d2 = 0.f, d3 = 0.f;
            #pragma unroll
            for (int kb = 0; kb < 4; kb++) {
                const uint4 b = sB[kb * 4 + nb][lane];
                mma_bf16(d0,dd1,d2,d3, ah[kb][0],ah[kb][1],ah[kb][2],ah[kb][3], b.x, b.y);
                mma_bf16(d0,dd1,d2,d3, ah[kb][0],ah[kb][1],ah[kb][2],ah[kb][3], b.z, b.w);
                mma_bf16(d0,dd1,d2,d3, al[kb][0],al[kb][1],al[kb][2],al[kb][3], b.x, b.y);
            }
            d1n[nb][0] = d0; d1n[nb][1] = dd1; d1n[nb][2] = d2; d1n[nb][3] = d3;
        }

        // epilogue for the PREVIOUS group (independent of d1n -> scheduler interleaves)
        epilogue(d1p, Rp, N, HW, invHW, lane, g, t, bb0, bb1, bb2,
                 &sG1[0][0], &sB1[0][0], &sW2H[0][0], &sW2L[0][0],
                 sW3F, sG2, sB2, out);

        #pragma unroll
        for (int nb = 0; nb < 4; nb++)
            #pragma unroll
            for (int j = 0; j < 4; j++) d1p[nb][j] = d1n[nb][j];
        Rp  = grp * 16;
        grp = nxt;
    }

    // ---- drain: epilogue for the final group ----
    epilogue(d1p, Rp, N, HW, invHW, lane, g, t, bb0, bb1, bb2,
             &sG1[0][0], &sB1[0][0], &sW2H[0][0], &sW2L[0][0],
             sW3F, sG2, sB2, out);
}

extern "C" void kernel_launch(void* const* d_in, const int* in_sizes, int n_in,
                              void* d_out, int out_size)
{
    const float* x  = (const float*)d_in[0];
    const float* w1 = (const float*)d_in[1];
    const float* g1 = (const float*)d_in[2];
    const float* b1 = (const float*)d_in[3];
    const float* w2 = (const float*)d_in[4];
    const float* g2 = (const float*)d_in[5];
    const float* b2 = (const float*)d_in[6];
    const float* w3 = (const float*)d_in[7];
    const float* b3 = (const float*)d_in[8];
    const int*   Bp = (const int*)d_in[9];

    const int N       = in_sizes[0] / 64;
    const int ngroups = (N + 15) / 16;
    int blocks = (ngroups + 3) / 4;
    if (blocks > NCTAS) blocks = NCTAS;

    fused_decoder_frag<<<blocks, TPB>>>(
        x, w1, g1, b1, w2, g2, b2, w3, b3, Bp,
        (float*)d_out, N, ngroups);
}